// round 14
// baseline (speedup 1.0000x reference)
#include <cuda_runtime.h>

#define ALPHA 0.01f

typedef unsigned long long u64;

// ---------------- global scratch ----------------
__device__ float g_oo[65536 * 5];               // obs_out (attention softmax result)
__device__ float g_gates[(size_t)65536 * 256];  // GEMM output [r|z|gi_n|gh_n]

__device__ __forceinline__ float lrelu(float v) { return fmaxf(v, ALPHA * v); }
__device__ __forceinline__ float fsig(float v)  { return __fdividef(1.0f, 1.0f + __expf(-v)); }
__device__ __forceinline__ float ftanh(float v) { return 1.0f - __fdividef(2.0f, __expf(2.0f * v) + 1.0f); }

__device__ __forceinline__ u64 pack2(float lo, float hi) {
    u64 r; asm("mov.b64 %0, {%1, %2};" : "=l"(r) : "f"(lo), "f"(hi)); return r;
}
__device__ __forceinline__ void unpack2(u64 v, float& lo, float& hi) {
    asm("mov.b64 {%0, %1}, %2;" : "=f"(lo), "=f"(hi) : "l"(v));
}
__device__ __forceinline__ u64 fma2(u64 a, u64 b, u64 c) {
    u64 d; asm("fma.rn.f32x2 %0, %1, %2, %3;" : "=l"(d) : "l"(a), "l"(b), "l"(c)); return d;
}

// ================= Kernel A: tokens -> attention -> obs_out =================
#define NBA    256
#define ROWSA  128
#define A_WIN   0
#define A_BIN   1536
#define A_WA1   1728
#define A_WA2   1792
#define A_WO1   1856
#define A_BO1   2176
#define A_WO2   2208
#define A_BO2   2720
#define A_WO3   2736
#define A_BO3   2752
#define A_OBS   2756
#define A_WHX   13636
#define A_HPV   16324
#define A_H1S   16964
#define A_TOT   (16964 + 8448)

__global__ void __launch_bounds__(NBA, 2)
stageA_kernel(const float* __restrict__ g_obs,
              const float* __restrict__ w_in0, const float* __restrict__ b_in0,
              const float* __restrict__ w_in1, const float* __restrict__ b_in1,
              const float* __restrict__ w_in2, const float* __restrict__ b_in2,
              const float* __restrict__ g_W,  const float* __restrict__ g_a,
              const float* __restrict__ w_o1, const float* __restrict__ b_o1,
              const float* __restrict__ w_o2, const float* __restrict__ b_o2,
              const float* __restrict__ w_o3, const float* __restrict__ b_o3)
{
    extern __shared__ float sm[];
    const int tid  = threadIdx.x;
    const int lrow = tid & 127;
    const int half = tid >> 7;
    const int row  = blockIdx.x * ROWSA + lrow;

    #define CPY4(off, src, n) { const float4* s4_ = (const float4*)(src); \
                                float4* d4_ = (float4*)&sm[off]; \
                                for (int i = tid; i < (n)/4; i += NBA) d4_[i] = s4_[i]; }
    CPY4(A_WIN,        w_in0, 512);
    CPY4(A_WIN + 512,  w_in1, 512);
    CPY4(A_WIN + 1024, w_in2, 512);
    CPY4(A_BIN,        b_in0, 64);
    CPY4(A_BIN + 64,   b_in1, 64);
    CPY4(A_BIN + 128,  b_in2, 64);
    CPY4(A_WO1, w_o1, 320);  CPY4(A_BO1, b_o1, 32);
    CPY4(A_WO2, w_o2, 512);  CPY4(A_BO2, b_o2, 16);
    CPY4(A_WO3, w_o3, 16);
    #undef CPY4
    if (tid == 0) sm[A_BO3] = b_o3[0];

    if (tid < 128) {
        const int j = tid & 63;
        const float* av = g_a + ((tid < 64) ? 0 : 64);
        const float* wr = g_W + j * 64;
        float s = 0.f;
        #pragma unroll 8
        for (int m = 0; m < 64; ++m) s = fmaf(wr[m], av[m], s);
        sm[((tid < 64) ? A_WA1 : A_WA2) + j] = s;
    }

    {
        const float4* src4 = (const float4*)(g_obs + (size_t)blockIdx.x * ROWSA * 85);
        float4* dst4 = (float4*)&sm[A_OBS];
        for (int i = tid; i < ROWSA * 85 / 4; i += NBA) dst4[i] = src4[i];
    }
    __syncthreads();

    const float* orow = &sm[A_OBS + lrow * 85];

    // ---- stage 1: 5 tokens per half, f32x2 over j-pairs ----
    #pragma unroll
    for (int tt = 0; tt < 5; ++tt) {
        const int sel = half ? ((tt < 4) ? 1 : 2) : 0;
        u64 o2[8];
        #pragma unroll
        for (int f = 0; f < 8; ++f) {
            int idx = half * 40 + tt * 8 + 4 + f;       // (t*8+f+4) % 80
            if (idx >= 80) idx -= 80;
            const float ov = orow[idx];
            o2[f] = pack2(ov, ov);
        }
        const ulonglong2* w2v  = (const ulonglong2*)&sm[A_WIN + sel * 512];
        const ulonglong2* b2v  = (const ulonglong2*)&sm[A_BIN + sel * 64];
        const ulonglong2* wa1v = (const ulonglong2*)&sm[A_WA1];
        const ulonglong2* wa2v = (const ulonglong2*)&sm[A_WA2];
        u64 s1a = 0ull, s2a = 0ull;
        #pragma unroll 4
        for (int pv = 0; pv < 16; ++pv) {              // 4 j per pv
            ulonglong2 bb = b2v[pv];
            u64 acc0 = bb.x, acc1 = bb.y;
            #pragma unroll
            for (int f = 0; f < 8; ++f) {
                ulonglong2 wv = w2v[f * 16 + pv];
                acc0 = fma2(o2[f], wv.x, acc0);
                acc1 = fma2(o2[f], wv.y, acc1);
            }
            float l0, u0, l1, u1;
            unpack2(acc0, l0, u0); unpack2(acc1, l1, u1);
            const u64 hm0 = pack2(lrelu(l0), lrelu(u0));
            const u64 hm1 = pack2(lrelu(l1), lrelu(u1));
            ulonglong2 a1 = wa1v[pv], a2 = wa2v[pv];
            s1a = fma2(hm0, a1.x, s1a); s1a = fma2(hm1, a1.y, s1a);
            s2a = fma2(hm0, a2.x, s2a); s2a = fma2(hm1, a2.y, s2a);
        }
        float s1l, s1h, s2l, s2h;
        unpack2(s1a, s1l, s1h); unpack2(s2a, s2l, s2h);
        const int t = half * 5 + tt;
        sm[A_WHX + lrow * 21 + 2 * t]     = s1l + s1h;
        sm[A_WHX + lrow * 21 + 2 * t + 1] = s2l + s2h;
    }
    __syncthreads();

    float wh1[10], wh2[10];
    #pragma unroll
    for (int t = 0; t < 10; ++t) {
        wh1[t] = sm[A_WHX + lrow * 21 + 2 * t];
        wh2[t] = sm[A_WHX + lrow * 21 + 2 * t + 1];
    }

    // ---- stage 2: attention rows (3 / 2 per half) ----
    float mx1[5], dinv1[5];
    #pragma unroll
    for (int c = 0; c < 5; ++c) {
        float mx = -1e30f;
        #pragma unroll
        for (int r2 = 0; r2 < 5; ++r2) mx = fmaxf(mx, lrelu(wh1[5 + c] + wh2[r2]));
        float d = 0.f;
        #pragma unroll
        for (int r2 = 0; r2 < 5; ++r2) d += __expf(lrelu(wh1[5 + c] + wh2[r2]) - mx);
        mx1[c] = mx; dinv1[c] = __fdividef(1.0f, d);
    }

    float* h1s = &sm[A_H1S + tid * 33];

    #pragma unroll
    for (int rr = 0; rr < 3; ++rr) {
        if (half && rr == 2) break;
        const int r = half ? (3 + rr) : rr;
        const float w1r = half ? wh1[3 + rr] : wh1[rr];
        const float w2r = half ? wh2[3 + rr] : wh2[rr];
        float att[10];
        {
            float ev[5]; float mx = -1e30f;
            #pragma unroll
            for (int c = 0; c < 5; ++c) {
                float v = lrelu(w1r + wh2[5 + c]);
                ev[c] = v; mx = fmaxf(mx, v);
            }
            float d = 0.f;
            #pragma unroll
            for (int c = 0; c < 5; ++c) { float e_ = __expf(ev[c] - mx); att[c] = e_; d += e_; }
            float inv = __fdividef(1.0f, d);
            #pragma unroll
            for (int c = 0; c < 5; ++c) att[c] *= inv;
            #pragma unroll
            for (int c = 0; c < 5; ++c)
                att[5 + c] = __expf(lrelu(wh1[5 + c] + w2r) - mx1[c]) * dinv1[c];
        }
        {
            const float4* wv4 = (const float4*)&sm[A_WO1];
            const float4* bv4 = (const float4*)&sm[A_BO1];
            #pragma unroll
            for (int jv = 0; jv < 8; ++jv) {
                float4 acc = bv4[jv];
                #pragma unroll
                for (int k = 0; k < 10; ++k) {
                    float4 wv = wv4[k * 8 + jv];
                    acc.x = fmaf(att[k], wv.x, acc.x);
                    acc.y = fmaf(att[k], wv.y, acc.y);
                    acc.z = fmaf(att[k], wv.z, acc.z);
                    acc.w = fmaf(att[k], wv.w, acc.w);
                }
                h1s[4*jv]   = lrelu(acc.x); h1s[4*jv+1] = lrelu(acc.y);
                h1s[4*jv+2] = lrelu(acc.z); h1s[4*jv+3] = lrelu(acc.w);
            }
        }
        float4 hacc[4];
        {
            const float4* wv4 = (const float4*)&sm[A_WO2];
            const float4* bv4 = (const float4*)&sm[A_BO2];
            #pragma unroll
            for (int jv = 0; jv < 4; ++jv) hacc[jv] = bv4[jv];
            #pragma unroll 4
            for (int k = 0; k < 32; ++k) {
                const float h1k = h1s[k];
                #pragma unroll
                for (int jv = 0; jv < 4; ++jv) {
                    float4 wv = wv4[k * 4 + jv];
                    hacc[jv].x = fmaf(h1k, wv.x, hacc[jv].x);
                    hacc[jv].y = fmaf(h1k, wv.y, hacc[jv].y);
                    hacc[jv].z = fmaf(h1k, wv.z, hacc[jv].z);
                    hacc[jv].w = fmaf(h1k, wv.w, hacc[jv].w);
                }
            }
        }
        float v = sm[A_BO3];
        {
            const float4* wv4 = (const float4*)&sm[A_WO3];
            #pragma unroll
            for (int jv = 0; jv < 4; ++jv) {
                float4 wv = wv4[jv];
                v = fmaf(lrelu(hacc[jv].x), wv.x, v);
                v = fmaf(lrelu(hacc[jv].y), wv.y, v);
                v = fmaf(lrelu(hacc[jv].z), wv.z, v);
                v = fmaf(lrelu(hacc[jv].w), wv.w, v);
            }
        }
        sm[A_HPV + lrow * 5 + r] = lrelu(v);
    }
    __syncthreads();

    if (!half) {
        float hp[5];
        #pragma unroll
        for (int r = 0; r < 5; ++r) hp[r] = sm[A_HPV + lrow * 5 + r];
        float mx = fmaxf(fmaxf(fmaxf(hp[0], hp[1]), fmaxf(hp[2], hp[3])), hp[4]);
        float e0 = __expf(hp[0] - mx), e1 = __expf(hp[1] - mx), e2 = __expf(hp[2] - mx);
        float e3 = __expf(hp[3] - mx), e4 = __expf(hp[4] - mx);
        float inv = __fdividef(1.0f, e0 + e1 + e2 + e3 + e4);
        float* op = &g_oo[(size_t)row * 5];
        op[0] = e0 * inv; op[1] = e1 * inv; op[2] = e2 * inv;
        op[3] = e3 * inv; op[4] = e4 * inv;
    }
}

// ================= Kernel G: fused fc1 + gate GEMM (row-pair vectorization) =================
#define G_THREADS 512
#define XP 130                      // Xs pitch
#define WP 258                      // Ws pitch
#define G_XS 0                      // 128*130 = 16640
#define G_WS 16640                  // 128*258 = 33024 (phase0/1: Os + Wf live here)
#define G_OS G_WS                   // obs tile k-major: 90*130 = 11700
#define G_WF (G_WS + 11700)         // w_fc1 5760 + bias 64
#define G_TOT (16640 + 33024)       // 49664 floats = 198656 bytes

__global__ void __launch_bounds__(G_THREADS, 1)
gemm_kernel(const float* __restrict__ g_obs, const float* __restrict__ g_hid,
            const float* __restrict__ w_fc1, const float* __restrict__ b_fc1,
            const float* __restrict__ w_ih, const float* __restrict__ w_hh)
{
    extern __shared__ float sm[];
    float* Xs = &sm[G_XS];
    float* Ws = &sm[G_WS];
    const int tid = threadIdx.x;
    const size_t rb = (size_t)blockIdx.x * 128;
    const int tr = tid >> 5;        // warp id -> rows [8tr, 8tr+8) = 4 row-pairs
    const int l  = tid & 31;        // lane -> col pair {2l, 2l+1}

    // ---- phase 0: stage h, obs, obs_out, w_fc1 ----
    for (int idx = tid; idx < 128 * 64; idx += G_THREADS) {
        const int r = idx >> 6, k = idx & 63;
        Xs[(64 + k) * XP + r] = g_hid[(rb + r) * 64 + k];
    }
    for (int idx = tid; idx < 128 * 85; idx += G_THREADS) {
        const int r = idx / 85, k = idx - r * 85;
        sm[G_OS + k * XP + r] = g_obs[(rb + r) * 85 + k];
    }
    for (int idx = tid; idx < 128 * 5; idx += G_THREADS) {
        const int r = idx / 5, m = idx - r * 5;
        sm[G_OS + (85 + m) * XP + r] = g_oo[(rb + r) * 5 + m];
    }
    for (int i = tid; i < 5760; i += G_THREADS) sm[G_WF + i] = w_fc1[i];
    if (tid < 64) sm[G_WF + 5760 + tid] = b_fc1[tid];
    __syncthreads();

    // ---- phase 1: fc1; acc = {rowEven, rowOdd} per col ----
    {
        u64 fac[4][2];
        {
            float b0, b1;
            unpack2(*(const u64*)&sm[G_WF + 5760 + 2 * l], b0, b1);
            const u64 i0 = pack2(b0, b0), i1 = pack2(b1, b1);
            #pragma unroll
            for (int i2 = 0; i2 < 4; ++i2) { fac[i2][0] = i0; fac[i2][1] = i1; }
        }
        #pragma unroll 2
        for (int k = 0; k < 90; ++k) {
            const float* ap = &sm[G_OS + k * XP + 8 * tr];
            const u64 a0 = *(const u64*)ap;          // {row0, row1}
            const u64 a1 = *(const u64*)(ap + 2);
            const u64 a2 = *(const u64*)(ap + 4);
            const u64 a3 = *(const u64*)(ap + 6);
            float w0, w1;
            unpack2(*(const u64*)&sm[G_WF + k * 64 + 2 * l], w0, w1);
            const u64 wd0 = pack2(w0, w0), wd1 = pack2(w1, w1);
            fac[0][0] = fma2(a0, wd0, fac[0][0]); fac[0][1] = fma2(a0, wd1, fac[0][1]);
            fac[1][0] = fma2(a1, wd0, fac[1][0]); fac[1][1] = fma2(a1, wd1, fac[1][1]);
            fac[2][0] = fma2(a2, wd0, fac[2][0]); fac[2][1] = fma2(a2, wd1, fac[2][1]);
            fac[3][0] = fma2(a3, wd0, fac[3][0]); fac[3][1] = fma2(a3, wd1, fac[3][1]);
        }
        #pragma unroll
        for (int i2 = 0; i2 < 4; ++i2) {
            float e0, o0, e1, o1;
            unpack2(fac[i2][0], e0, o0);
            unpack2(fac[i2][1], e1, o1);
            *(u64*)&Xs[(2 * l)     * XP + 8 * tr + 2 * i2] = pack2(fmaxf(e0, 0.f), fmaxf(o0, 0.f));
            *(u64*)&Xs[(2 * l + 1) * XP + 8 * tr + 2 * i2] = pack2(fmaxf(e1, 0.f), fmaxf(o1, 0.f));
        }
    }
    __syncthreads();

    // ---- phase 2: stage Ws (overwrites Os/Wf) ----
    for (int idx = tid; idx < 64 * 192; idx += G_THREADS) {
        const int k = idx & 63, t = idx >> 6;           // t = source gate row 0..191
        Ws[k * WP + t] = w_ih[t * 64 + k];              // k<64 block: r,z,gi_n
        const int dt = (t < 128) ? t : (t + 64);        // n-rows go to gh_n slots
        Ws[(64 + k) * WP + dt] = w_hh[t * 64 + k];      // k>=64 block: r,z,gh_n
    }
    __syncthreads();

    // ---- phase 3: gate GEMM, row-pair accumulators ----
    u64 aR[4][2], aZ[4][2], aNi[4][2], aNh[4][2];
    #pragma unroll
    for (int i2 = 0; i2 < 4; ++i2) {
        aR[i2][0] = aR[i2][1] = 0ull; aZ[i2][0] = aZ[i2][1] = 0ull;
        aNi[i2][0] = aNi[i2][1] = 0ull; aNh[i2][0] = aNh[i2][1] = 0ull;
    }

    #pragma unroll 2
    for (int k = 0; k < 64; ++k) {
        const float* ap = &Xs[k * XP + 8 * tr];
        const u64 a0 = *(const u64*)ap;
        const u64 a1 = *(const u64*)(ap + 2);
        const u64 a2 = *(const u64*)(ap + 4);
        const u64 a3 = *(const u64*)(ap + 6);
        const float* wp = &Ws[k * WP + 2 * l];
        float r0, r1, z0, z1, n0, n1;
        unpack2(*(const u64*)wp,         r0, r1);
        unpack2(*(const u64*)(wp + 64),  z0, z1);
        unpack2(*(const u64*)(wp + 128), n0, n1);
        const u64 rd0 = pack2(r0, r0), rd1 = pack2(r1, r1);
        const u64 zd0 = pack2(z0, z0), zd1 = pack2(z1, z1);
        const u64 nd0 = pack2(n0, n0), nd1 = pack2(n1, n1);
        #define KROW(i2, av) { \
            aR[i2][0]  = fma2(av, rd0, aR[i2][0]);  aR[i2][1]  = fma2(av, rd1, aR[i2][1]); \
            aZ[i2][0]  = fma2(av, zd0, aZ[i2][0]);  aZ[i2][1]  = fma2(av, zd1, aZ[i2][1]); \
            aNi[i2][0] = fma2(av, nd0, aNi[i2][0]); aNi[i2][1] = fma2(av, nd1, aNi[i2][1]); }
        KROW(0, a0) KROW(1, a1) KROW(2, a2) KROW(3, a3)
        #undef KROW
    }
    #pragma unroll 2
    for (int k = 64; k < 128; ++k) {
        const float* ap = &Xs[k * XP + 8 * tr];
        const u64 a0 = *(const u64*)ap;
        const u64 a1 = *(const u64*)(ap + 2);
        const u64 a2 = *(const u64*)(ap + 4);
        const u64 a3 = *(const u64*)(ap + 6);
        const float* wp = &Ws[k * WP + 2 * l];
        float r0, r1, z0, z1, n0, n1;
        unpack2(*(const u64*)wp,         r0, r1);
        unpack2(*(const u64*)(wp + 64),  z0, z1);
        unpack2(*(const u64*)(wp + 192), n0, n1);
        const u64 rd0 = pack2(r0, r0), rd1 = pack2(r1, r1);
        const u64 zd0 = pack2(z0, z0), zd1 = pack2(z1, z1);
        const u64 nd0 = pack2(n0, n0), nd1 = pack2(n1, n1);
        #define KROW(i2, av) { \
            aR[i2][0]  = fma2(av, rd0, aR[i2][0]);  aR[i2][1]  = fma2(av, rd1, aR[i2][1]); \
            aZ[i2][0]  = fma2(av, zd0, aZ[i2][0]);  aZ[i2][1]  = fma2(av, zd1, aZ[i2][1]); \
            aNh[i2][0] = fma2(av, nd0, aNh[i2][0]); aNh[i2][1] = fma2(av, nd1, aNh[i2][1]); }
        KROW(0, a0) KROW(1, a1) KROW(2, a2) KROW(3, a3)
        #undef KROW
    }

    // ---- store: repack row-pair accs into {colE,colO} per row, STG.64 coalesced ----
    #pragma unroll
    for (int i2 = 0; i2 < 4; ++i2) {
        const size_t rE = rb + 8 * tr + 2 * i2;
        float e0, o0, e1, o1;
        #define STORE_GATE(acc, goff) { \
            unpack2(acc[i2][0], e0, o0); \
            unpack2(acc[i2][1], e1, o1); \
            *(u64*)&g_gates[rE * 256 + (goff) + 2 * l]       = pack2(e0, e1); \
            *(u64*)&g_gates[(rE + 1) * 256 + (goff) + 2 * l] = pack2(o0, o1); }
        STORE_GATE(aR,  0)
        STORE_GATE(aZ,  64)
        STORE_GATE(aNi, 128)
        STORE_GATE(aNh, 192)
        #undef STORE_GATE
    }
}

// ================= Kernel E: GRU epilogue + q =================
__global__ void __launch_bounds__(256, 4)
epi_kernel(const float* __restrict__ g_hid,
           const float* __restrict__ b_ih, const float* __restrict__ b_hh,
           const float* __restrict__ w_fc2, const float* __restrict__ b_fc2,
           float* __restrict__ out_q, float* __restrict__ out_h)
{
    __shared__ float sbih[192], sbhh[192], swf[320], sb5[8];
    const int tid = threadIdx.x;
    for (int i = tid; i < 192; i += 256) { sbih[i] = b_ih[i]; sbhh[i] = b_hh[i]; }
    for (int i = tid; i < 320; i += 256) swf[i] = w_fc2[i];
    if (tid < 5) sb5[tid] = b_fc2[tid];
    __syncthreads();

    const int w    = tid >> 5;
    const int lane = tid & 31;
    const size_t row = (size_t)blockIdx.x * 8 + w;
    const float* gp = &g_gates[row * 256];
    const float* hp = g_hid + row * 64;
    float* ho = out_h + row * 64;

    float hq0 = 0.f, hq1 = 0.f, hq2 = 0.f, hq3 = 0.f, hq4 = 0.f;
    #pragma unroll
    for (int jj = 0; jj < 2; ++jj) {
        const int j = lane + 32 * jj;
        const float g0 = gp[j], g1 = gp[64 + j], g2 = gp[128 + j], g3 = gp[192 + j];
        const float r_ = fsig(g0 + sbih[j] + sbhh[j]);
        const float z_ = fsig(g1 + sbih[64 + j] + sbhh[64 + j]);
        const float n_ = ftanh(g2 + sbih[128 + j] + r_ * (g3 + sbhh[128 + j]));
        const float hj = hp[j];
        const float h_ = n_ + z_ * (hj - n_);
        ho[j] = h_;
        hq0 = fmaf(h_, swf[j * 5],     hq0);
        hq1 = fmaf(h_, swf[j * 5 + 1], hq1);
        hq2 = fmaf(h_, swf[j * 5 + 2], hq2);
        hq3 = fmaf(h_, swf[j * 5 + 3], hq3);
        hq4 = fmaf(h_, swf[j * 5 + 4], hq4);
    }
    #pragma unroll
    for (int off = 16; off; off >>= 1) {
        hq0 += __shfl_down_sync(0xffffffffu, hq0, off);
        hq1 += __shfl_down_sync(0xffffffffu, hq1, off);
        hq2 += __shfl_down_sync(0xffffffffu, hq2, off);
        hq3 += __shfl_down_sync(0xffffffffu, hq3, off);
        hq4 += __shfl_down_sync(0xffffffffu, hq4, off);
    }
    if (lane == 0) {
        float* qp = out_q + row * 5;
        qp[0] = hq0 + sb5[0]; qp[1] = hq1 + sb5[1]; qp[2] = hq2 + sb5[2];
        qp[3] = hq3 + sb5[3]; qp[4] = hq4 + sb5[4];
    }
}

extern "C" void kernel_launch(void* const* d_in, const int* in_sizes, int n_in,
                              void* d_out, int out_size)
{
    const float* g_obs  = (const float*)d_in[0];
    const float* g_hid  = (const float*)d_in[1];
    const float* w_in0  = (const float*)d_in[2];
    const float* b_in0  = (const float*)d_in[3];
    const float* w_in1  = (const float*)d_in[4];
    const float* b_in1  = (const float*)d_in[5];
    const float* w_in2  = (const float*)d_in[6];
    const float* b_in2  = (const float*)d_in[7];
    const float* g_W    = (const float*)d_in[8];
    const float* g_a    = (const float*)d_in[9];
    const float* w_o1   = (const float*)d_in[10];
    const float* b_o1   = (const float*)d_in[11];
    const float* w_o2   = (const float*)d_in[12];
    const float* b_o2   = (const float*)d_in[13];
    const float* w_o3   = (const float*)d_in[14];
    const float* b_o3   = (const float*)d_in[15];
    const float* w_fc1  = (const float*)d_in[16];
    const float* b_fc1  = (const float*)d_in[17];
    const float* w_ih   = (const float*)d_in[18];
    const float* w_hh   = (const float*)d_in[19];
    const float* b_ih   = (const float*)d_in[20];
    const float* b_hh   = (const float*)d_in[21];
    const float* w_fc2  = (const float*)d_in[22];
    const float* b_fc2  = (const float*)d_in[23];

    float* out   = (float*)d_out;
    float* out_q = out;                          // q: (65536, 5)
    float* out_h = out + (size_t)65536 * 5;      // h: (65536, 64)

    const int smemA = A_TOT * 4;                 // 101648 B (2 blocks/SM)
    const int smemG = G_TOT * 4;                 // 198656 B
    cudaFuncSetAttribute(stageA_kernel, cudaFuncAttributeMaxDynamicSharedMemorySize, smemA);
    cudaFuncSetAttribute(gemm_kernel,   cudaFuncAttributeMaxDynamicSharedMemorySize, smemG);

    stageA_kernel<<<65536 / ROWSA, NBA, smemA>>>(
        g_obs, w_in0, b_in0, w_in1, b_in1, w_in2, b_in2, g_W, g_a,
        w_o1, b_o1, w_o2, b_o2, w_o3, b_o3);

    gemm_kernel<<<65536 / 128, G_THREADS, smemG>>>(
        g_obs, g_hid, w_fc1, b_fc1, w_ih, w_hh);

    epi_kernel<<<65536 / 8, 256>>>(g_hid, b_ih, b_hh, w_fc2, b_fc2, out_q, out_h);
}

// round 15
// speedup vs baseline: 1.0062x; 1.0062x over previous
#include <cuda_runtime.h>

#define ALPHA 0.01f

typedef unsigned long long u64;

// ---------------- global scratch ----------------
__device__ float g_oo[65536 * 5];               // obs_out (attention softmax result)
__device__ float g_gates[(size_t)65536 * 256];  // GEMM output [r|z|gi_n|gh_n]

__device__ __forceinline__ float lrelu(float v) { return fmaxf(v, ALPHA * v); }
__device__ __forceinline__ float fsig(float v)  { return __fdividef(1.0f, 1.0f + __expf(-v)); }
__device__ __forceinline__ float ftanh(float v) { return 1.0f - __fdividef(2.0f, __expf(2.0f * v) + 1.0f); }

__device__ __forceinline__ u64 pack2(float lo, float hi) {
    u64 r; asm("mov.b64 %0, {%1, %2};" : "=l"(r) : "f"(lo), "f"(hi)); return r;
}
__device__ __forceinline__ void unpack2(u64 v, float& lo, float& hi) {
    asm("mov.b64 {%0, %1}, %2;" : "=f"(lo), "=f"(hi) : "l"(v));
}
__device__ __forceinline__ u64 fma2(u64 a, u64 b, u64 c) {
    u64 d; asm("fma.rn.f32x2 %0, %1, %2, %3;" : "=l"(d) : "l"(a), "l"(b), "l"(c)); return d;
}

// ================= Kernel A: tokens -> attention -> obs_out =================
#define NBA    256
#define ROWSA  128
#define A_WIN   0        // 1536
#define A_BIN   1536     // 192
#define A_WA1   1728     // 64
#define A_WA2   1792     // 64
#define A_WO1   1856     // 320
#define A_BO1   2176     // 32
#define A_WO2   2208     // 512
#define A_BO2   2720     // 16
#define A_WO3   2736     // 16
#define A_BO3   2752     // 1 (+3)
#define A_OBS   2756     // 128*85 = 10880; reused as h1 scratch (stride 34) after stage 1
#define A_WHX   13636    // 128*21 = 2688
#define A_HPV   16324    // 128*5  = 640
#define A_TOT   16964    // floats = 67856 bytes

__global__ void __launch_bounds__(NBA, 2)
stageA_kernel(const float* __restrict__ g_obs,
              const float* __restrict__ w_in0, const float* __restrict__ b_in0,
              const float* __restrict__ w_in1, const float* __restrict__ b_in1,
              const float* __restrict__ w_in2, const float* __restrict__ b_in2,
              const float* __restrict__ g_W,  const float* __restrict__ g_a,
              const float* __restrict__ w_o1, const float* __restrict__ b_o1,
              const float* __restrict__ w_o2, const float* __restrict__ b_o2,
              const float* __restrict__ w_o3, const float* __restrict__ b_o3)
{
    extern __shared__ float sm[];
    const int tid  = threadIdx.x;
    const int lrow = tid & 127;
    const int half = tid >> 7;
    const int row  = blockIdx.x * ROWSA + lrow;

    #define CPY4(off, src, n) { const float4* s4_ = (const float4*)(src); \
                                float4* d4_ = (float4*)&sm[off]; \
                                for (int i = tid; i < (n)/4; i += NBA) d4_[i] = s4_[i]; }
    CPY4(A_WIN,        w_in0, 512);
    CPY4(A_WIN + 512,  w_in1, 512);
    CPY4(A_WIN + 1024, w_in2, 512);
    CPY4(A_BIN,        b_in0, 64);
    CPY4(A_BIN + 64,   b_in1, 64);
    CPY4(A_BIN + 128,  b_in2, 64);
    CPY4(A_WO1, w_o1, 320);  CPY4(A_BO1, b_o1, 32);
    CPY4(A_WO2, w_o2, 512);  CPY4(A_BO2, b_o2, 16);
    CPY4(A_WO3, w_o3, 16);
    #undef CPY4
    if (tid == 0) sm[A_BO3] = b_o3[0];

    if (tid < 128) {
        const int j = tid & 63;
        const float* av = g_a + ((tid < 64) ? 0 : 64);
        const float* wr = g_W + j * 64;
        float s = 0.f;
        #pragma unroll 8
        for (int m = 0; m < 64; ++m) s = fmaf(wr[m], av[m], s);
        sm[((tid < 64) ? A_WA1 : A_WA2) + j] = s;
    }

    {
        const float4* src4 = (const float4*)(g_obs + (size_t)blockIdx.x * ROWSA * 85);
        float4* dst4 = (float4*)&sm[A_OBS];
        for (int i = tid; i < ROWSA * 85 / 4; i += NBA) dst4[i] = src4[i];
    }
    __syncthreads();

    const float* orow = &sm[A_OBS + lrow * 85];

    // ---- stage 1: 5 tokens per half, f32x2 over j-pairs ----
    #pragma unroll
    for (int tt = 0; tt < 5; ++tt) {
        const int sel = half ? ((tt < 4) ? 1 : 2) : 0;
        u64 o2[8];
        #pragma unroll
        for (int f = 0; f < 8; ++f) {
            int idx = half * 40 + tt * 8 + 4 + f;       // (t*8+f+4) % 80
            if (idx >= 80) idx -= 80;
            const float ov = orow[idx];
            o2[f] = pack2(ov, ov);
        }
        const ulonglong2* w2v  = (const ulonglong2*)&sm[A_WIN + sel * 512];
        const ulonglong2* b2v  = (const ulonglong2*)&sm[A_BIN + sel * 64];
        const ulonglong2* wa1v = (const ulonglong2*)&sm[A_WA1];
        const ulonglong2* wa2v = (const ulonglong2*)&sm[A_WA2];
        u64 s1a = 0ull, s2a = 0ull;
        #pragma unroll 4
        for (int pv = 0; pv < 16; ++pv) {
            ulonglong2 bb = b2v[pv];
            u64 acc0 = bb.x, acc1 = bb.y;
            #pragma unroll
            for (int f = 0; f < 8; ++f) {
                ulonglong2 wv = w2v[f * 16 + pv];
                acc0 = fma2(o2[f], wv.x, acc0);
                acc1 = fma2(o2[f], wv.y, acc1);
            }
            float l0, u0, l1, u1;
            unpack2(acc0, l0, u0); unpack2(acc1, l1, u1);
            const u64 hm0 = pack2(lrelu(l0), lrelu(u0));
            const u64 hm1 = pack2(lrelu(l1), lrelu(u1));
            ulonglong2 a1 = wa1v[pv], a2 = wa2v[pv];
            s1a = fma2(hm0, a1.x, s1a); s1a = fma2(hm1, a1.y, s1a);
            s2a = fma2(hm0, a2.x, s2a); s2a = fma2(hm1, a2.y, s2a);
        }
        float s1l, s1h, s2l, s2h;
        unpack2(s1a, s1l, s1h); unpack2(s2a, s2l, s2h);
        const int t = half * 5 + tt;
        sm[A_WHX + lrow * 21 + 2 * t]     = s1l + s1h;
        sm[A_WHX + lrow * 21 + 2 * t + 1] = s2l + s2h;
    }
    __syncthreads();   // wh visible; obs region now dead -> reuse as h1 scratch

    // wh accessors: stay in SHARED (register diet). stride 21 -> conflict-free.
    const float* whb = &sm[A_WHX + lrow * 21];
    #define WH1(t) whb[2 * (t)]
    #define WH2(t) whb[2 * (t) + 1]

    // ---- stage 2: attention rows (3 / 2 per half) ----
    float mx1[5], dinv1[5];
    #pragma unroll
    for (int c = 0; c < 5; ++c) {
        float mx = -1e30f;
        #pragma unroll
        for (int r2 = 0; r2 < 5; ++r2) mx = fmaxf(mx, lrelu(WH1(5 + c) + WH2(r2)));
        float d = 0.f;
        #pragma unroll
        for (int r2 = 0; r2 < 5; ++r2) d += __expf(lrelu(WH1(5 + c) + WH2(r2)) - mx);
        mx1[c] = mx; dinv1[c] = __fdividef(1.0f, d);
    }

    float* h1s = &sm[A_OBS + tid * 34];   // u64-aligned per-thread scratch (deg-2 conflicts)

    #pragma unroll
    for (int rr = 0; rr < 3; ++rr) {
        if (half && rr == 2) break;
        const int r = half ? (3 + rr) : rr;
        const float w1r = WH1(r);
        const float w2r = WH2(r);
        u64 att2[10];
        {
            float ev[5]; float mx = -1e30f;
            #pragma unroll
            for (int c = 0; c < 5; ++c) {
                float v = lrelu(w1r + WH2(5 + c));
                ev[c] = v; mx = fmaxf(mx, v);
            }
            float d = 0.f;
            float av[5];
            #pragma unroll
            for (int c = 0; c < 5; ++c) { float e_ = __expf(ev[c] - mx); av[c] = e_; d += e_; }
            float inv = __fdividef(1.0f, d);
            #pragma unroll
            for (int c = 0; c < 5; ++c) { float a = av[c] * inv; att2[c] = pack2(a, a); }
            #pragma unroll
            for (int c = 0; c < 5; ++c) {
                float a = __expf(lrelu(WH1(5 + c) + w2r) - mx1[c]) * dinv1[c];
                att2[5 + c] = pack2(a, a);
            }
        }
        // h1 = lrelu(att @ w_o1 + b_o1), f32x2 j-pairs -> shared scratch
        #pragma unroll
        for (int pv = 0; pv < 16; ++pv) {
            u64 acc = *(const u64*)&sm[A_BO1 + 2 * pv];
            #pragma unroll
            for (int k = 0; k < 10; ++k)
                acc = fma2(att2[k], *(const u64*)&sm[A_WO1 + k * 32 + 2 * pv], acc);
            float x0, x1;
            unpack2(acc, x0, x1);
            *(u64*)&h1s[2 * pv] = pack2(lrelu(x0), lrelu(x1));
        }
        // h2 = lrelu(h1 @ w_o2 + b_o2), f32x2, k-outer
        u64 hacc2[8];
        {
            const ulonglong2* b2 = (const ulonglong2*)&sm[A_BO2];
            #pragma unroll
            for (int p = 0; p < 4; ++p) { ulonglong2 q = b2[p]; hacc2[2*p] = q.x; hacc2[2*p+1] = q.y; }
            #pragma unroll 4
            for (int k = 0; k < 32; ++k) {
                const float h1k = h1s[k];
                const u64 h2k = pack2(h1k, h1k);
                const ulonglong2* wq = (const ulonglong2*)&sm[A_WO2 + k * 16];
                #pragma unroll
                for (int p = 0; p < 4; ++p) {
                    ulonglong2 q = wq[p];
                    hacc2[2*p]   = fma2(h2k, q.x, hacc2[2*p]);
                    hacc2[2*p+1] = fma2(h2k, q.y, hacc2[2*p+1]);
                }
            }
        }
        float v = sm[A_BO3];
        #pragma unroll
        for (int p = 0; p < 8; ++p) {
            float a, b;
            unpack2(hacc2[p], a, b);
            v = fmaf(lrelu(a), sm[A_WO3 + 2 * p],     v);
            v = fmaf(lrelu(b), sm[A_WO3 + 2 * p + 1], v);
        }
        sm[A_HPV + lrow * 5 + r] = lrelu(v);
    }
    __syncthreads();

    if (!half) {
        float hp[5];
        #pragma unroll
        for (int r = 0; r < 5; ++r) hp[r] = sm[A_HPV + lrow * 5 + r];
        float mx = fmaxf(fmaxf(fmaxf(hp[0], hp[1]), fmaxf(hp[2], hp[3])), hp[4]);
        float e0 = __expf(hp[0] - mx), e1 = __expf(hp[1] - mx), e2 = __expf(hp[2] - mx);
        float e3 = __expf(hp[3] - mx), e4 = __expf(hp[4] - mx);
        float inv = __fdividef(1.0f, e0 + e1 + e2 + e3 + e4);
        float* op = &g_oo[(size_t)row * 5];
        op[0] = e0 * inv; op[1] = e1 * inv; op[2] = e2 * inv;
        op[3] = e3 * inv; op[4] = e4 * inv;
    }
    #undef WH1
    #undef WH2
}

// ================= Kernel G: fused fc1 + gate GEMM (row-pair vectorization) =================
#define G_THREADS 512
#define XP 132                      // Xs pitch (mod 4 == 0 -> 16B-aligned A loads)
#define WP 258                      // Ws pitch
#define G_XS 0                      // 128*132 = 16896
#define G_WS 16896                  // 128*258 = 33024 (phase0/1: Os + Wf live here)
#define G_OS G_WS                   // obs tile k-major: 90*132 = 11880
#define G_WF (G_WS + 11880)         // w_fc1 5760 + bias 64
#define G_TOT (16896 + 33024)       // 49920 floats = 199680 bytes

__global__ void __launch_bounds__(G_THREADS, 1)
gemm_kernel(const float* __restrict__ g_obs, const float* __restrict__ g_hid,
            const float* __restrict__ w_fc1, const float* __restrict__ b_fc1,
            const float* __restrict__ w_ih, const float* __restrict__ w_hh)
{
    extern __shared__ float sm[];
    float* Xs = &sm[G_XS];
    float* Ws = &sm[G_WS];
    const int tid = threadIdx.x;
    const size_t rb = (size_t)blockIdx.x * 128;
    const int tr = tid >> 5;        // warp id -> rows [8tr, 8tr+8) = 4 row-pairs
    const int l  = tid & 31;        // lane -> col pair {2l, 2l+1}

    // ---- phase 0: stage h, obs, obs_out, w_fc1 ----
    for (int idx = tid; idx < 128 * 64; idx += G_THREADS) {
        const int r = idx >> 6, k = idx & 63;
        Xs[(64 + k) * XP + r] = g_hid[(rb + r) * 64 + k];
    }
    for (int idx = tid; idx < 128 * 85; idx += G_THREADS) {
        const int r = idx / 85, k = idx - r * 85;
        sm[G_OS + k * XP + r] = g_obs[(rb + r) * 85 + k];
    }
    for (int idx = tid; idx < 128 * 5; idx += G_THREADS) {
        const int r = idx / 5, m = idx - r * 5;
        sm[G_OS + (85 + m) * XP + r] = g_oo[(rb + r) * 5 + m];
    }
    for (int i = tid; i < 5760; i += G_THREADS) sm[G_WF + i] = w_fc1[i];
    if (tid < 64) sm[G_WF + 5760 + tid] = b_fc1[tid];
    __syncthreads();

    // ---- phase 1: fc1; acc = {rowEven, rowOdd} per col ----
    {
        u64 fac[4][2];
        {
            float b0, b1;
            unpack2(*(const u64*)&sm[G_WF + 5760 + 2 * l], b0, b1);
            const u64 i0 = pack2(b0, b0), i1 = pack2(b1, b1);
            #pragma unroll
            for (int i2 = 0; i2 < 4; ++i2) { fac[i2][0] = i0; fac[i2][1] = i1; }
        }
        #pragma unroll 4
        for (int k = 0; k < 90; ++k) {
            const ulonglong2* ap2 = (const ulonglong2*)&sm[G_OS + k * XP + 8 * tr];
            const ulonglong2 q0 = ap2[0];        // {row0,row1},{row2,row3}
            const ulonglong2 q1 = ap2[1];
            float w0, w1;
            unpack2(*(const u64*)&sm[G_WF + k * 64 + 2 * l], w0, w1);
            const u64 wd0 = pack2(w0, w0), wd1 = pack2(w1, w1);
            fac[0][0] = fma2(q0.x, wd0, fac[0][0]); fac[0][1] = fma2(q0.x, wd1, fac[0][1]);
            fac[1][0] = fma2(q0.y, wd0, fac[1][0]); fac[1][1] = fma2(q0.y, wd1, fac[1][1]);
            fac[2][0] = fma2(q1.x, wd0, fac[2][0]); fac[2][1] = fma2(q1.x, wd1, fac[2][1]);
            fac[3][0] = fma2(q1.y, wd0, fac[3][0]); fac[3][1] = fma2(q1.y, wd1, fac[3][1]);
        }
        #pragma unroll
        for (int i2 = 0; i2 < 4; ++i2) {
            float e0, o0, e1, o1;
            unpack2(fac[i2][0], e0, o0);
            unpack2(fac[i2][1], e1, o1);
            *(u64*)&Xs[(2 * l)     * XP + 8 * tr + 2 * i2] = pack2(fmaxf(e0, 0.f), fmaxf(o0, 0.f));
            *(u64*)&Xs[(2 * l + 1) * XP + 8 * tr + 2 * i2] = pack2(fmaxf(e1, 0.f), fmaxf(o1, 0.f));
        }
    }
    __syncthreads();

    // ---- phase 2: stage Ws (overwrites Os/Wf) ----
    for (int idx = tid; idx < 64 * 192; idx += G_THREADS) {
        const int k = idx & 63, t = idx >> 6;           // t = source gate row 0..191
        Ws[k * WP + t] = w_ih[t * 64 + k];              // k<64 block: r,z,gi_n
        const int dt = (t < 128) ? t : (t + 64);        // n-rows go to gh_n slots
        Ws[(64 + k) * WP + dt] = w_hh[t * 64 + k];      // k>=64 block: r,z,gh_n
    }
    __syncthreads();

    // ---- phase 3: gate GEMM, row-pair accumulators ----
    u64 aR[4][2], aZ[4][2], aNi[4][2], aNh[4][2];
    #pragma unroll
    for (int i2 = 0; i2 < 4; ++i2) {
        aR[i2][0] = aR[i2][1] = 0ull; aZ[i2][0] = aZ[i2][1] = 0ull;
        aNi[i2][0] = aNi[i2][1] = 0ull; aNh[i2][0] = aNh[i2][1] = 0ull;
    }

    #pragma unroll 4
    for (int k = 0; k < 64; ++k) {
        const ulonglong2* ap2 = (const ulonglong2*)&Xs[k * XP + 8 * tr];
        const ulonglong2 q0 = ap2[0];
        const ulonglong2 q1 = ap2[1];
        const float* wp = &Ws[k * WP + 2 * l];
        float r0, r1, z0, z1, n0, n1;
        unpack2(*(const u64*)wp,         r0, r1);
        unpack2(*(const u64*)(wp + 64),  z0, z1);
        unpack2(*(const u64*)(wp + 128), n0, n1);
        const u64 rd0 = pack2(r0, r0), rd1 = pack2(r1, r1);
        const u64 zd0 = pack2(z0, z0), zd1 = pack2(z1, z1);
        const u64 nd0 = pack2(n0, n0), nd1 = pack2(n1, n1);
        #define KROW(i2, av) { \
            aR[i2][0]  = fma2(av, rd0, aR[i2][0]);  aR[i2][1]  = fma2(av, rd1, aR[i2][1]); \
            aZ[i2][0]  = fma2(av, zd0, aZ[i2][0]);  aZ[i2][1]  = fma2(av, zd1, aZ[i2][1]); \
            aNi[i2][0] = fma2(av, nd0, aNi[i2][0]); aNi[i2][1] = fma2(av, nd1, aNi[i2][1]); }
        KROW(0, q0.x) KROW(1, q0.y) KROW(2, q1.x) KROW(3, q1.y)
        #undef KROW
    }
    #pragma unroll 4
    for (int k = 64; k < 128; ++k) {
        const ulonglong2* ap2 = (const ulonglong2*)&Xs[k * XP + 8 * tr];
        const ulonglong2 q0 = ap2[0];
        const ulonglong2 q1 = ap2[1];
        const float* wp = &Ws[k * WP + 2 * l];
        float r0, r1, z0, z1, n0, n1;
        unpack2(*(const u64*)wp,         r0, r1);
        unpack2(*(const u64*)(wp + 64),  z0, z1);
        unpack2(*(const u64*)(wp + 192), n0, n1);
        const u64 rd0 = pack2(r0, r0), rd1 = pack2(r1, r1);
        const u64 zd0 = pack2(z0, z0), zd1 = pack2(z1, z1);
        const u64 nd0 = pack2(n0, n0), nd1 = pack2(n1, n1);
        #define KROW(i2, av) { \
            aR[i2][0]  = fma2(av, rd0, aR[i2][0]);  aR[i2][1]  = fma2(av, rd1, aR[i2][1]); \
            aZ[i2][0]  = fma2(av, zd0, aZ[i2][0]);  aZ[i2][1]  = fma2(av, zd1, aZ[i2][1]); \
            aNh[i2][0] = fma2(av, nd0, aNh[i2][0]); aNh[i2][1] = fma2(av, nd1, aNh[i2][1]); }
        KROW(0, q0.x) KROW(1, q0.y) KROW(2, q1.x) KROW(3, q1.y)
        #undef KROW
    }

    // ---- store: repack row-pair accs into {colE,colO} per row, STG.64 coalesced ----
    #pragma unroll
    for (int i2 = 0; i2 < 4; ++i2) {
        const size_t rE = rb + 8 * tr + 2 * i2;
        float e0, o0, e1, o1;
        #define STORE_GATE(acc, goff) { \
            unpack2(acc[i2][0], e0, o0); \
            unpack2(acc[i2][1], e1, o1); \
            *(u64*)&g_gates[rE * 256 + (goff) + 2 * l]       = pack2(e0, e1); \
            *(u64*)&g_gates[(rE + 1) * 256 + (goff) + 2 * l] = pack2(o0, o1); }
        STORE_GATE(aR,  0)
        STORE_GATE(aZ,  64)
        STORE_GATE(aNi, 128)
        STORE_GATE(aNh, 192)
        #undef STORE_GATE
    }
}

// ================= Kernel E: GRU epilogue + q =================
__global__ void __launch_bounds__(256, 4)
epi_kernel(const float* __restrict__ g_hid,
           const float* __restrict__ b_ih, const float* __restrict__ b_hh,
           const float* __restrict__ w_fc2, const float* __restrict__ b_fc2,
           float* __restrict__ out_q, float* __restrict__ out_h)
{
    __shared__ float sbih[192], sbhh[192], swf[320], sb5[8];
    const int tid = threadIdx.x;
    for (int i = tid; i < 192; i += 256) { sbih[i] = b_ih[i]; sbhh[i] = b_hh[i]; }
    for (int i = tid; i < 320; i += 256) swf[i] = w_fc2[i];
    if (tid < 5) sb5[tid] = b_fc2[tid];
    __syncthreads();

    const int w    = tid >> 5;
    const int lane = tid & 31;
    const size_t row = (size_t)blockIdx.x * 8 + w;
    const float* gp = &g_gates[row * 256];
    const float* hp = g_hid + row * 64;
    float* ho = out_h + row * 64;

    float hq0 = 0.f, hq1 = 0.f, hq2 = 0.f, hq3 = 0.f, hq4 = 0.f;
    #pragma unroll
    for (int jj = 0; jj < 2; ++jj) {
        const int j = lane + 32 * jj;
        const float g0 = gp[j], g1 = gp[64 + j], g2 = gp[128 + j], g3 = gp[192 + j];
        const float r_ = fsig(g0 + sbih[j] + sbhh[j]);
        const float z_ = fsig(g1 + sbih[64 + j] + sbhh[64 + j]);
        const float n_ = ftanh(g2 + sbih[128 + j] + r_ * (g3 + sbhh[128 + j]));
        const float hj = hp[j];
        const float h_ = n_ + z_ * (hj - n_);
        ho[j] = h_;
        hq0 = fmaf(h_, swf[j * 5],     hq0);
        hq1 = fmaf(h_, swf[j * 5 + 1], hq1);
        hq2 = fmaf(h_, swf[j * 5 + 2], hq2);
        hq3 = fmaf(h_, swf[j * 5 + 3], hq3);
        hq4 = fmaf(h_, swf[j * 5 + 4], hq4);
    }
    #pragma unroll
    for (int off = 16; off; off >>= 1) {
        hq0 += __shfl_down_sync(0xffffffffu, hq0, off);
        hq1 += __shfl_down_sync(0xffffffffu, hq1, off);
        hq2 += __shfl_down_sync(0xffffffffu, hq2, off);
        hq3 += __shfl_down_sync(0xffffffffu, hq3, off);
        hq4 += __shfl_down_sync(0xffffffffu, hq4, off);
    }
    if (lane == 0) {
        float* qp = out_q + row * 5;
        qp[0] = hq0 + sb5[0]; qp[1] = hq1 + sb5[1]; qp[2] = hq2 + sb5[2];
        qp[3] = hq3 + sb5[3]; qp[4] = hq4 + sb5[4];
    }
}

extern "C" void kernel_launch(void* const* d_in, const int* in_sizes, int n_in,
                              void* d_out, int out_size)
{
    const float* g_obs  = (const float*)d_in[0];
    const float* g_hid  = (const float*)d_in[1];
    const float* w_in0  = (const float*)d_in[2];
    const float* b_in0  = (const float*)d_in[3];
    const float* w_in1  = (const float*)d_in[4];
    const float* b_in1  = (const float*)d_in[5];
    const float* w_in2  = (const float*)d_in[6];
    const float* b_in2  = (const float*)d_in[7];
    const float* g_W    = (const float*)d_in[8];
    const float* g_a    = (const float*)d_in[9];
    const float* w_o1   = (const float*)d_in[10];
    const float* b_o1   = (const float*)d_in[11];
    const float* w_o2   = (const float*)d_in[12];
    const float* b_o2   = (const float*)d_in[13];
    const float* w_o3   = (const float*)d_in[14];
    const float* b_o3   = (const float*)d_in[15];
    const float* w_fc1  = (const float*)d_in[16];
    const float* b_fc1  = (const float*)d_in[17];
    const float* w_ih   = (const float*)d_in[18];
    const float* w_hh   = (const float*)d_in[19];
    const float* b_ih   = (const float*)d_in[20];
    const float* b_hh   = (const float*)d_in[21];
    const float* w_fc2  = (const float*)d_in[22];
    const float* b_fc2  = (const float*)d_in[23];

    float* out   = (float*)d_out;
    float* out_q = out;                          // q: (65536, 5)
    float* out_h = out + (size_t)65536 * 5;      // h: (65536, 64)

    const int smemA = A_TOT * 4;                 // 67856 B (2 blocks/SM)
    const int smemG = G_TOT * 4;                 // 199680 B
    cudaFuncSetAttribute(stageA_kernel, cudaFuncAttributeMaxDynamicSharedMemorySize, smemA);
    cudaFuncSetAttribute(gemm_kernel,   cudaFuncAttributeMaxDynamicSharedMemorySize, smemG);

    stageA_kernel<<<65536 / ROWSA, NBA, smemA>>>(
        g_obs, w_in0, b_in0, w_in1, b_in1, w_in2, b_in2, g_W, g_a,
        w_o1, b_o1, w_o2, b_o2, w_o3, b_o3);

    gemm_kernel<<<65536 / 128, G_THREADS, smemG>>>(
        g_obs, g_hid, w_fc1, b_fc1, w_ih, w_hh);

    epi_kernel<<<65536 / 8, 256>>>(g_hid, b_ih, b_hh, w_fc2, b_fc2, out_q, out_h);
}